// round 17
// baseline (speedup 1.0000x reference)
#include <cuda_runtime.h>

// ConceptGaussians: per-domain gather.
//   labels  : [B=2097152, 8] int32 in [0,64)
//   mean/log_var : [8, 64] f32
// Output: [ means[B,8] | log_vars[B,8] ] f32.
//
// R14: R11's winning shape (1 sample/thread, 256 TPB, no smem, no loop) with
// the two tables FUSED into one __device__ float2 table (built by a tiny prep
// kernel once per launch). 16 LDG.32 gathers + 16 addr IMADs become
// 8 LDG.64 gathers + 8 IMADs: same cache lines touched, half the issue
// slots and dependency chain, zero per-block prologue.

#define TPB 256

__device__ float2 g_tab[512];   // fused (mean, log_var), 4 KiB, L1-resident

__global__ void prep_kernel(const float* __restrict__ g_mean,
                            const float* __restrict__ g_lv)
{
    int i = threadIdx.x;        // one block of 512
    g_tab[i] = make_float2(g_mean[i], g_lv[i]);
}

__global__ void __launch_bounds__(TPB, 8)   // cap regs at 32 -> full occupancy
concept_gather_kernel(const int4* __restrict__ lab4,
                      float4* __restrict__ out_m,
                      float4* __restrict__ out_v,
                      int n)
{
    int b = blockIdx.x * TPB + threadIdx.x;
    if (b >= n) return;

    // 8 labels: two coalesced LDG.128.
    int4 c0 = lab4[2 * b];
    int4 c1 = lab4[2 * b + 1];

    // 8 fused gathers (LDG.64), domain d at g_tab[d*64 + idx].
    float2 t0 = __ldg(&g_tab[       c0.x]);
    float2 t1 = __ldg(&g_tab[ 64 +  c0.y]);
    float2 t2 = __ldg(&g_tab[128 +  c0.z]);
    float2 t3 = __ldg(&g_tab[192 +  c0.w]);
    float2 t4 = __ldg(&g_tab[256 +  c1.x]);
    float2 t5 = __ldg(&g_tab[320 +  c1.y]);
    float2 t6 = __ldg(&g_tab[384 +  c1.z]);
    float2 t7 = __ldg(&g_tab[448 +  c1.w]);

    // Coalesced STG.128 into the two output halves.
    out_m[2 * b]     = make_float4(t0.x, t1.x, t2.x, t3.x);
    out_m[2 * b + 1] = make_float4(t4.x, t5.x, t6.x, t7.x);
    out_v[2 * b]     = make_float4(t0.y, t1.y, t2.y, t3.y);
    out_v[2 * b + 1] = make_float4(t4.y, t5.y, t6.y, t7.y);
}

extern "C" void kernel_launch(void* const* d_in, const int* in_sizes, int n_in,
                              void* d_out, int out_size)
{
    const int4*  labels = (const int4*)d_in[0];   // [B,8] int32 as 2x int4
    const float* g_mean = (const float*)d_in[1];  // [8,64]
    const float* g_lv   = (const float*)d_in[2];  // [8,64]

    int n = in_sizes[0] / 8;                      // B samples

    float4* out_m = (float4*)d_out;               // means half
    float4* out_v = out_m + (size_t)n * 2;        // log_var half

    prep_kernel<<<1, 512>>>(g_mean, g_lv);        // build fused table (4 KiB)

    int blocks = (n + TPB - 1) / TPB;             // 8192 for B=2M
    concept_gather_kernel<<<blocks, TPB>>>(labels, out_m, out_v, n);
}